// round 9
// baseline (speedup 1.0000x reference)
#include <cuda_runtime.h>
#include <cuda_bf16.h>
#include <math.h>
#include <cstdint>

#define Bb 64
#define Ff 256
#define Tt 1024
#define Hh 1024
#define Oo 512
#define RNCTA 64          // recurrence CTAs (co-resident single wave)
#define NCOL 16           // hidden columns per recurrence CTA
#define KC 256            // k elements per streamed S chunk
#define NCHUNK (Hh / KC)  // 4
#define GRPSZ (RNCTA / NCHUNK)            // 16 CTAs per producer group
#define SSTR 528          // S chunk smem row stride bytes (512 + 16 pad)
#define WSTR 2064         // Wh smem row stride bytes (2048 + 16 pad)
#define CHUNK_BYTES (64 * SSTR)           // 33792
#define OFF_WHI 0
#define OFF_WLO 33024                     // 16 * WSTR
#define OFF_CH  66048
#define OFF_RED (OFF_CH + 4 * CHUNK_BYTES)      // 201216
#define SMEM_TOTAL (OFF_RED + 16 * 32 * 16)     // + 8KB reduction = 209408

typedef unsigned long long ull;

// ---------------- device globals (no allocation allowed) ----------------
__device__ float g_xT[(size_t)Tt * Bb * Ff];          // x as (T,B,F)
__device__ float g_U [(size_t)Tt * Hh * Bb];          // U then fp32 states, [t][h][b]
__device__ __nv_bfloat16 g_WhiT[(size_t)Hh * Hh];     // Wh^T hi  [h][k]
__device__ __nv_bfloat16 g_WloT[(size_t)Hh * Hh];     // Wh^T lo  [h][k]
__device__ __nv_bfloat16 g_Sh[2][(size_t)Bb * Hh];    // state hi, [buf][b][k]
__device__ __nv_bfloat16 g_Sl[2][(size_t)Bb * Hh];    // state lo
__device__ unsigned int g_cnt;                        // legacy grid barrier (end only)
__device__ unsigned int g_sense;
__device__ unsigned int g_grpcnt[NCHUNK];             // producer-group arrival counters

// ---------------- helpers ----------------
__device__ __forceinline__ uint32_t smem_u32(const void* p) {
    uint32_t a;
    asm("{ .reg .u64 t; cvta.to.shared.u64 t, %1; cvt.u32.u64 %0, t; }" : "=r"(a) : "l"(p));
    return a;
}
__device__ __forceinline__ float ftanh(float x) {
    float xc = fminf(fmaxf(x, -15.0f), 15.0f);
    float e  = __expf(2.0f * xc);
    return __fdividef(e - 1.0f, e + 1.0f);
}
__device__ __forceinline__ ull pk2(float lo, float hi) {
    ull r; asm("mov.b64 %0, {%1, %2};" : "=l"(r) : "f"(lo), "f"(hi)); return r;
}
__device__ __forceinline__ ull ffma2(ull a, ull b, ull c) {
    ull d; asm("fma.rn.f32x2 %0, %1, %2, %3;" : "=l"(d) : "l"(a), "l"(b), "l"(c)); return d;
}
__device__ __forceinline__ float2 upk2(ull v) {
    float2 f; asm("mov.b64 {%0, %1}, %2;" : "=f"(f.x), "=f"(f.y) : "l"(v)); return f;
}

// mma.sync m16n8k16 bf16 -> fp32 (base ISA on compute_103)
__device__ __forceinline__ void mma16816(float* d, const uint32_t* a, uint32_t b0, uint32_t b1) {
    asm volatile("mma.sync.aligned.m16n8k16.row.col.f32.bf16.bf16.f32 "
        "{%0,%1,%2,%3}, {%4,%5,%6,%7}, {%8,%9}, {%0,%1,%2,%3};"
        : "+f"(d[0]), "+f"(d[1]), "+f"(d[2]), "+f"(d[3])
        : "r"(a[0]), "r"(a[1]), "r"(a[2]), "r"(a[3]), "r"(b0), "r"(b1));
}
__device__ __forceinline__ void ldsm4(uint32_t* r, uint32_t addr) {
    asm volatile("ldmatrix.sync.aligned.m8n8.x4.shared.b16 {%0,%1,%2,%3}, [%4];"
        : "=r"(r[0]), "=r"(r[1]), "=r"(r[2]), "=r"(r[3]) : "r"(addr));
}
__device__ __forceinline__ void cpasync16(uint32_t dst, const void* src) {
    asm volatile("cp.async.cg.shared.global [%0], [%1], 16;" :: "r"(dst), "l"(src));
}
#define CP_COMMIT() asm volatile("cp.async.commit_group;" ::: "memory")
#define CP_WAIT(n)  asm volatile("cp.async.wait_group %0;" :: "n"(n) : "memory")

// CTA-wide acquire-wait on a producer-group counter. Observation happens on
// tid0 ONLY (volatile spin, exactly like the proven gridbar), followed by
// __threadfence (acquire) and __syncthreads (CTA-wide broadcast of the
// ordering). No thread issues chunk loads until the barrier releases.
__device__ __forceinline__ void wait_chunk(int g, unsigned target) {
    if (threadIdx.x == 0) {
        while (*((volatile unsigned int*)&g_grpcnt[g]) < target) { }
        __threadfence();
    }
    __syncthreads();
}

// ---------------- legacy grid barrier (used twice at kernel end) ----------------
__device__ __forceinline__ void gridbar(unsigned s) {
    __syncthreads();
    if (threadIdx.x == 0) {
        __threadfence();
        unsigned prev = atomicAdd(&g_cnt, 1u);
        if (prev == RNCTA - 1) {
            atomicExch(&g_cnt, 0u);
            __threadfence();
            atomicExch(&g_sense, s);
        } else {
            while (*((volatile unsigned int*)&g_sense) != s) { }
        }
        __threadfence();
    }
    __syncthreads();
}

// ---------------- prep kernels ----------------
__global__ void transpose_x_kernel(const float* __restrict__ x) {
    __shared__ float tile[32][33];
    int b = blockIdx.z, t0 = blockIdx.x * 32, f0 = blockIdx.y * 32;
    const float* xb = x + (size_t)b * Ff * Tt;
    for (int i = threadIdx.y; i < 32; i += 8)
        tile[i][threadIdx.x] = xb[(size_t)(f0 + i) * Tt + t0 + threadIdx.x];
    __syncthreads();
    for (int i = threadIdx.y; i < 32; i += 8)
        g_xT[((size_t)(t0 + i) * Bb + b) * Ff + f0 + threadIdx.x] = tile[threadIdx.x][i];
}

// Wh (k,h) fp32 -> WhT hi/lo bf16 [h][k]
__global__ void whsplit_kernel(const float* __restrict__ Wh) {
    __shared__ float tile[32][33];
    int k0 = blockIdx.x * 32, h0 = blockIdx.y * 32;
    for (int i = threadIdx.y; i < 32; i += 8)
        tile[i][threadIdx.x] = Wh[(size_t)(k0 + i) * Hh + h0 + threadIdx.x];
    __syncthreads();
    for (int i = threadIdx.y; i < 32; i += 8) {
        float w = tile[threadIdx.x][i];
        __nv_bfloat16 hi = __float2bfloat16(w);
        size_t idx = (size_t)(h0 + i) * Hh + k0 + threadIdx.x;
        g_WhiT[idx] = hi;
        g_WloT[idx] = __float2bfloat16(w - __bfloat162float(hi));
    }
}

// U[t][h][b] = bias[h] + sum_f xT[t][b][f] * Wx[f][h]   (f32x2 SIMT GEMM)
__global__ __launch_bounds__(256) void u_gemm_kernel(const float* __restrict__ Wx,
                                                     const float* __restrict__ bias) {
    const int t  = blockIdx.y;
    const int h0 = blockIdx.x * 64;
    __shared__ __align__(16) float As[16][68];
    __shared__ __align__(16) float Bs[16][68];
    const int tid = threadIdx.x;
    const int tx = tid & 15, ty = tid >> 4;
    const int ar = tid >> 4, ac = (tid & 15) * 4;
    const int bbr = tid >> 2, bf = (tid & 3) * 4;
    const float* Xr = g_xT + ((size_t)t * Bb + bbr) * Ff;

    ull acc[4][2];
    #pragma unroll
    for (int i = 0; i < 4; ++i) { acc[i][0] = 0ull; acc[i][1] = 0ull; }
    float4 ra = *(const float4*)(Wx + (size_t)ar * Hh + h0 + ac);
    float4 rb = *(const float4*)(Xr + bf);

    for (int k0 = 0; k0 < Ff; k0 += 16) {
        *(float4*)&As[ar][ac] = ra;
        Bs[bf + 0][bbr] = rb.x; Bs[bf + 1][bbr] = rb.y;
        Bs[bf + 2][bbr] = rb.z; Bs[bf + 3][bbr] = rb.w;
        __syncthreads();
        if (k0 + 16 < Ff) {
            ra = *(const float4*)(Wx + (size_t)(k0 + 16 + ar) * Hh + h0 + ac);
            rb = *(const float4*)(Xr + k0 + 16 + bf);
        }
        #pragma unroll
        for (int kk = 0; kk < 16; ++kk) {
            float4 a = *(const float4*)&As[kk][4 * ty];
            ulonglong2 b2 = *(const ulonglong2*)&Bs[kk][4 * tx];
            float av[4] = {a.x, a.y, a.z, a.w};
            #pragma unroll
            for (int i = 0; i < 4; ++i) {
                ull sp = pk2(av[i], av[i]);
                acc[i][0] = ffma2(sp, b2.x, acc[i][0]);
                acc[i][1] = ffma2(sp, b2.y, acc[i][1]);
            }
        }
        __syncthreads();
    }
    #pragma unroll
    for (int i = 0; i < 4; ++i) {
        float bv = bias[h0 + 4 * ty + i];
        float2 lo = upk2(acc[i][0]), hi = upk2(acc[i][1]);
        float4 v = make_float4(lo.x + bv, lo.y + bv, hi.x + bv, hi.y + bv);
        *(float4*)&g_U[((size_t)t * Hh + h0 + 4 * ty + i) * Bb + 4 * tx] = v;
    }
}

// ---------------- persistent mma.sync recurrence (counter-synced) ----------------
__device__ __forceinline__ void load_chunk(uint32_t sb, int buf, int c, int z, int tid) {
    #pragma unroll
    for (int i = 0; i < 8; ++i) {
        int seg = tid + i * 512;                  // 0..4095
        int mat = seg >> 11;                      // 0 hi, 1 lo
        int within = seg & 2047;
        int row = within >> 5, u = within & 31;
        const __nv_bfloat16* src = mat
            ? &g_Sl[z][(size_t)row * Hh + c * KC + u * 8]
            : &g_Sh[z][(size_t)row * Hh + c * KC + u * 8];
        uint32_t dst = sb + OFF_CH + (uint32_t)(buf * 2 + mat) * CHUNK_BYTES
                     + (uint32_t)row * SSTR + (uint32_t)u * 16;
        cpasync16(dst, src);
    }
    CP_COMMIT();
}

__global__ __launch_bounds__(512, 1) void rnn_mma_kernel() {
    extern __shared__ __align__(1024) char smem[];
    const uint32_t sb = smem_u32(smem);
    const int tid   = threadIdx.x;
    const int w     = tid >> 5;
    const int lane  = tid & 31;
    const int tile  = w & 7;                  // 8 output tiles
    const int khalf = w >> 3;                 // 0: even 32-k strips, 1: odd
    const int n0    = blockIdx.x * NCOL;
    const int grp   = blockIdx.x / GRPSZ;     // producer group of this CTA's columns
    const int m0    = (tile & 3) * 16;
    const int nw    = (tile >> 2) * 8;

    // stage Wh^T hi/lo slice (rows n0..n0+15)
    for (int q = tid; q < 16 * 128; q += 512) {
        int r = q >> 7, u = q & 127;
        *(float4*)(smem + OFF_WHI + r * WSTR + u * 16) =
            ((const float4*)g_WhiT)[(size_t)(n0 + r) * 128 + u];
        *(float4*)(smem + OFF_WLO + r * WSTR + u * 16) =
            ((const float4*)g_WloT)[(size_t)(n0 + r) * 128 + u];
    }

    // t = 0: state = tanh(U[0]), then arrive on own group counter (release)
    for (int e = tid; e < NCOL * Bb; e += 512) {
        int h = e >> 6, b = e & 63;
        size_t ui = (size_t)(n0 + h) * Bb + b;
        float v = ftanh(g_U[ui]);
        g_U[ui] = v;
        __nv_bfloat16 hi = __float2bfloat16(v);
        g_Sh[0][(size_t)b * Hh + n0 + h] = hi;
        g_Sl[0][(size_t)b * Hh + n0 + h] = __float2bfloat16(v - __bfloat162float(hi));
    }
    __threadfence();
    __syncthreads();
    if (tid == 0) { __threadfence(); atomicAdd(&g_grpcnt[grp], 1u); }

    // per-lane fragment geometry
    const uint32_t rowA  = (uint32_t)(m0 + (lane & 7) + ((lane >> 3) & 1) * 8);
    const uint32_t laneK = (uint32_t)((lane >> 4) * 16);          // bytes
    const uint32_t wBhi  = sb + OFF_WHI + (uint32_t)(nw + (lane & 7)) * WSTR
                         + (uint32_t)((lane >> 3) * 16);
    const uint32_t wBlo  = wBhi + (OFF_WLO - OFF_WHI);
    const int r0 = m0 + (lane >> 2);
    const int cA = n0 + nw + 2 * (lane & 3);

    for (int t = 1; t < Tt; ++t) {
        const int zread  = (t - 1) & 1;
        const int zwrite = t & 1;
        const unsigned tgt = (unsigned)t * GRPSZ;   // group ready for step t

        // chunk order rotated by group: waits and L2 traffic spread across chunks
        int cc0 = grp;                               // first chunk index
        wait_chunk(cc0, tgt);                        // tid0 spin + fence + syncthreads
        load_chunk(sb, 0, cc0, zread, tid);

        // prefetch U[t] for epilogue lanes (khalf==0 warps)
        float u00, u01, u10, u11;
        if (khalf == 0) {
            u00 = g_U[((size_t)t * Hh + cA) * Bb + r0];
            u01 = g_U[((size_t)t * Hh + cA + 1) * Bb + r0];
            u10 = g_U[((size_t)t * Hh + cA) * Bb + r0 + 8];
            u11 = g_U[((size_t)t * Hh + cA + 1) * Bb + r0 + 8];
        }

        float ahh[4] = {0.f, 0.f, 0.f, 0.f};
        float ahl[4] = {0.f, 0.f, 0.f, 0.f};
        float alh[4] = {0.f, 0.f, 0.f, 0.f};

        for (int c = 0; c < NCHUNK; ++c) {
            const int cc = (grp + c) & (NCHUNK - 1);       // actual chunk index
            if (c + 1 < NCHUNK) {
                const int cn = (grp + c + 1) & (NCHUNK - 1);
                wait_chunk(cn, tgt);                        // CTA-wide acquire
                load_chunk(sb, (c + 1) & 1, cn, zread, tid);
                CP_WAIT(1);
            } else {
                CP_WAIT(0);
            }
            __syncthreads();
            uint32_t ah = sb + OFF_CH + (uint32_t)((c & 1) * 2) * CHUNK_BYTES
                        + rowA * SSTR + laneK;
            uint32_t al = ah + CHUNK_BYTES;
            #pragma unroll
            for (int kq = 0; kq < 4; ++kq) {
                int kp = khalf + 2 * kq;
                uint32_t bh[4], bl[4];
                uint32_t kglob2 = (uint32_t)(cc * KC + kp * 32) * 2;
                ldsm4(bh, wBhi + kglob2);
                ldsm4(bl, wBlo + kglob2);
                #pragma unroll
                for (int s = 0; s < 2; ++s) {
                    uint32_t ahi[4], alo[4];
                    uint32_t kl2 = (uint32_t)(kp * 32 + s * 16) * 2;
                    ldsm4(ahi, ah + kl2);
                    ldsm4(alo, al + kl2);
                    mma16816(ahh, ahi, bh[2 * s], bh[2 * s + 1]);
                    mma16816(ahl, ahi, bl[2 * s], bl[2 * s + 1]);
                    mma16816(alh, alo, bh[2 * s], bh[2 * s + 1]);
                }
            }
            __syncthreads();
        }

        float acc[4];
        #pragma unroll
        for (int i = 0; i < 4; ++i) acc[i] = ahh[i] + ahl[i] + alh[i];

        if (khalf == 1) {
            *(float4*)(smem + OFF_RED + (uint32_t)(tile * 32 + lane) * 16) =
                make_float4(acc[0], acc[1], acc[2], acc[3]);
        }
        __syncthreads();

        if (khalf == 0) {
            float4 p = *(const float4*)(smem + OFF_RED + (uint32_t)(tile * 32 + lane) * 16);
            float s00 = ftanh(u00 + acc[0] + p.x);
            float s01 = ftanh(u01 + acc[1] + p.y);
            float s10 = ftanh(u10 + acc[2] + p.z);
            float s11 = ftanh(u11 + acc[3] + p.w);
            g_U[((size_t)t * Hh + cA) * Bb + r0]         = s00;
            g_U[((size_t)t * Hh + cA + 1) * Bb + r0]     = s01;
            g_U[((size_t)t * Hh + cA) * Bb + r0 + 8]     = s10;
            g_U[((size_t)t * Hh + cA + 1) * Bb + r0 + 8] = s11;
            {
                __nv_bfloat16 h0 = __float2bfloat16(s00), h1 = __float2bfloat16(s01);
                __nv_bfloat162 hp; hp.x = h0; hp.y = h1;
                __nv_bfloat162 lp;
                lp.x = __float2bfloat16(s00 - __bfloat162float(h0));
                lp.y = __float2bfloat16(s01 - __bfloat162float(h1));
                *(__nv_bfloat162*)&g_Sh[zwrite][(size_t)r0 * Hh + cA] = hp;
                *(__nv_bfloat162*)&g_Sl[zwrite][(size_t)r0 * Hh + cA] = lp;
            }
            {
                __nv_bfloat16 h0 = __float2bfloat16(s10), h1 = __float2bfloat16(s11);
                __nv_bfloat162 hp; hp.x = h0; hp.y = h1;
                __nv_bfloat162 lp;
                lp.x = __float2bfloat16(s10 - __bfloat162float(h0));
                lp.y = __float2bfloat16(s11 - __bfloat162float(h1));
                *(__nv_bfloat162*)&g_Sh[zwrite][(size_t)(r0 + 8) * Hh + cA] = hp;
                *(__nv_bfloat162*)&g_Sl[zwrite][(size_t)(r0 + 8) * Hh + cA] = lp;
            }
        }
        // release: this CTA's slice of S_t is visible -> arrive on group counter
        __threadfence();
        __syncthreads();
        if (tid == 0) { __threadfence(); atomicAdd(&g_grpcnt[grp], 1u); }
    }

    // drain + deterministic counter reset (graph-replay safe)
    gridbar(1u);
    if (blockIdx.x == 0 && tid < NCHUNK) g_grpcnt[tid] = 0u;
    gridbar(0u);
}

// ---------------- output projection (f32x2 SIMT) ----------------
__global__ __launch_bounds__(256) void out_gemm_kernel(const float* __restrict__ Wout,
                                                       const float* __restrict__ bout,
                                                       float* __restrict__ out) {
    const int t  = blockIdx.y;
    const int o0 = blockIdx.x * 64;
    __shared__ __align__(16) float As[16][68];
    __shared__ __align__(16) float Bs[16][68];
    const int tid = threadIdx.x;
    const int tx = tid & 15, ty = tid >> 4;
    const int r = tid >> 4, c = (tid & 15) * 4;

    ull acc[4][2];
    #pragma unroll
    for (int i = 0; i < 4; ++i) { acc[i][0] = 0ull; acc[i][1] = 0ull; }
    float4 ra = *(const float4*)&g_U[((size_t)t * Hh + r) * Bb + c];
    float4 rb = *(const float4*)(Wout + (size_t)r * Oo + o0 + c);

    for (int k0 = 0; k0 < Hh; k0 += 16) {
        *(float4*)&As[r][c] = ra;
        *(float4*)&Bs[r][c] = rb;
        __syncthreads();
        if (k0 + 16 < Hh) {
            ra = *(const float4*)&g_U[((size_t)t * Hh + k0 + 16 + r) * Bb + c];
            rb = *(const float4*)(Wout + (size_t)(k0 + 16 + r) * Oo + o0 + c);
        }
        #pragma unroll
        for (int kk = 0; kk < 16; ++kk) {
            float4 a = *(const float4*)&As[kk][4 * ty];
            ulonglong2 b2 = *(const ulonglong2*)&Bs[kk][4 * tx];
            float av[4] = {a.x, a.y, a.z, a.w};
            #pragma unroll
            for (int i = 0; i < 4; ++i) {
                ull sp = pk2(av[i], av[i]);
                acc[i][0] = ffma2(sp, b2.x, acc[i][0]);
                acc[i][1] = ffma2(sp, b2.y, acc[i][1]);
            }
        }
        __syncthreads();
    }
    float4 bo = *(const float4*)(bout + o0 + 4 * tx);
    #pragma unroll
    for (int i = 0; i < 4; ++i) {
        float2 lo = upk2(acc[i][0]), hi = upk2(acc[i][1]);
        float4 v = make_float4(lo.x + bo.x, lo.y + bo.y, hi.x + bo.z, hi.y + bo.w);
        int b = 4 * ty + i;
        *(float4*)&out[((size_t)b * Tt + t) * Oo + o0 + 4 * tx] = v;
    }
}

// ---------------- host ----------------
extern "C" void kernel_launch(void* const* d_in, const int* in_sizes, int n_in,
                              void* d_out, int out_size) {
    const float* x    = (const float*)d_in[0];
    const float* Wx   = (const float*)d_in[1];
    const float* Wh   = (const float*)d_in[2];
    const float* bias = (const float*)d_in[3];
    const float* Wout = (const float*)d_in[4];
    const float* bout = (const float*)d_in[5];
    float* out = (float*)d_out;

    cudaFuncSetAttribute(rnn_mma_kernel, cudaFuncAttributeMaxDynamicSharedMemorySize, SMEM_TOTAL);

    transpose_x_kernel<<<dim3(Tt / 32, Ff / 32, Bb), dim3(32, 8)>>>(x);
    whsplit_kernel    <<<dim3(Hh / 32, Hh / 32),     dim3(32, 8)>>>(Wh);
    u_gemm_kernel     <<<dim3(Hh / 64, Tt), 256>>>(Wx, bias);
    rnn_mma_kernel    <<<RNCTA, 512, SMEM_TOTAL>>>();
    out_gemm_kernel   <<<dim3(Oo / 64, Tt), 256>>>(Wout, bout, out);
}

// round 11
// speedup vs baseline: 1.3413x; 1.3413x over previous
#include <cuda_runtime.h>
#include <cuda.h>
#include <cuda_bf16.h>
#include <math.h>
#include <cstdint>

#define Bb 64
#define Ff 256
#define Tt 1024
#define Hh 1024
#define Oo 512
#define RNCTA 64          // recurrence CTAs (co-resident single wave)
#define NCOL 16           // hidden columns per recurrence CTA
#define KC 256            // k elements per chunk (quarter of Hh)
#define NCHUNK (Hh / KC)  // 4
#define WSTR 2064         // Wh smem row stride bytes (2048 + 16 pad)

// SMEM layout
#define OFF_WHI 0
#define OFF_WLO 33024                     // 16 * WSTR
#define MB_BASE 66048                     // 2 mbarriers @ +0, +8
#define OFF_S   66560                     // 1024-aligned; 2 buffers x 64KB
#define BUF_BYTES 65536                   // per buffer: hi 32KB + lo 32KB
#define OFF_RED (OFF_S + 2 * BUF_BYTES)   // 197632
#define SMEM_TOTAL (OFF_RED + 16 * 32 * 16)   // 205824

typedef unsigned long long ull;

// ---------------- device globals (no allocation allowed) ----------------
__device__ float g_xT[(size_t)Tt * Bb * Ff];          // x as (T,B,F)
__device__ float g_U [(size_t)Tt * Hh * Bb];          // U then fp32 states, [t][h][b]
__device__ __nv_bfloat16 g_WhiT[(size_t)Hh * Hh];     // Wh^T hi  [h][k]
__device__ __nv_bfloat16 g_WloT[(size_t)Hh * Hh];     // Wh^T lo  [h][k]
__device__ __nv_bfloat16 g_Sh[2][(size_t)Bb * Hh];    // state hi, [buf][b][k]
__device__ __nv_bfloat16 g_Sl[2][(size_t)Bb * Hh];    // state lo
__device__ unsigned int g_cnt;                        // grid barrier ({0,0} at end)
__device__ unsigned int g_sense;

// ---------------- helpers ----------------
__device__ __forceinline__ uint32_t smem_u32(const void* p) {
    uint32_t a;
    asm("{ .reg .u64 t; cvta.to.shared.u64 t, %1; cvt.u32.u64 %0, t; }" : "=r"(a) : "l"(p));
    return a;
}
__device__ __forceinline__ float ftanh(float x) {
    float xc = fminf(fmaxf(x, -15.0f), 15.0f);
    float e  = __expf(2.0f * xc);
    return __fdividef(e - 1.0f, e + 1.0f);
}
__device__ __forceinline__ ull pk2(float lo, float hi) {
    ull r; asm("mov.b64 %0, {%1, %2};" : "=l"(r) : "f"(lo), "f"(hi)); return r;
}
__device__ __forceinline__ ull ffma2(ull a, ull b, ull c) {
    ull d; asm("fma.rn.f32x2 %0, %1, %2, %3;" : "=l"(d) : "l"(a), "l"(b), "l"(c)); return d;
}
__device__ __forceinline__ float2 upk2(ull v) {
    float2 f; asm("mov.b64 {%0, %1}, %2;" : "=f"(f.x), "=f"(f.y) : "l"(v)); return f;
}

// mma.sync m16n8k16 bf16 -> fp32 (base ISA on compute_103)
__device__ __forceinline__ void mma16816(float* d, const uint32_t* a, uint32_t b0, uint32_t b1) {
    asm volatile("mma.sync.aligned.m16n8k16.row.col.f32.bf16.bf16.f32 "
        "{%0,%1,%2,%3}, {%4,%5,%6,%7}, {%8,%9}, {%0,%1,%2,%3};"
        : "+f"(d[0]), "+f"(d[1]), "+f"(d[2]), "+f"(d[3])
        : "r"(a[0]), "r"(a[1]), "r"(a[2]), "r"(a[3]), "r"(b0), "r"(b1));
}
__device__ __forceinline__ void ldsm4(uint32_t* r, uint32_t addr) {
    asm volatile("ldmatrix.sync.aligned.m8n8.x4.shared.b16 {%0,%1,%2,%3}, [%4];"
        : "=r"(r[0]), "=r"(r[1]), "=r"(r[2]), "=r"(r[3]) : "r"(addr));
}

// ---------------- TMA / mbarrier (base-ISA, compiled OK in R3) ----------------
#define MBARRIER_INIT(mbar, count) \
    asm volatile("mbarrier.init.shared.b64 [%0], %1;" \
        :: "r"((uint32_t)(mbar)), "r"((uint32_t)(count)) : "memory")
#define MBARRIER_EXPECT_TX(mbar, tx) \
    asm volatile("mbarrier.arrive.expect_tx.shared.b64 _, [%0], %1;" \
        :: "r"((uint32_t)(mbar)), "r"((uint32_t)(tx)) : "memory")
#define MBARRIER_WAIT_PARITY(mbar, parity) do {                                    \
    uint32_t _m = (uint32_t)(mbar), _p = (uint32_t)(parity), _done;                \
    asm volatile("{\n\t.reg .pred p;\n\t"                                          \
        "mbarrier.try_wait.parity.acquire.cta.shared::cta.b64 p, [%1], %2;\n\t"    \
        "selp.b32 %0, 1, 0, p;\n\t}"                                               \
        : "=r"(_done) : "r"(_m), "r"(_p) : "memory");                              \
    if (!_done) {                                                                  \
        asm volatile("{\n\t.reg .pred P1;\n\t"                                     \
            "WL_%=:\n\t"                                                           \
            "mbarrier.try_wait.parity.acquire.cta.shared::cta.b64 P1, [%0], %1, 0x989680;\n\t" \
            "@P1 bra.uni WD_%=;\n\t"                                               \
            "bra.uni WL_%=;\n\t"                                                   \
            "WD_%=:\n\t}" :: "r"(_m), "r"(_p) : "memory");                         \
    }                                                                              \
} while (0)
#define TMA_LOAD_3D(smem_addr, tmap, cx, cy, cz, mbar) \
    asm volatile("cp.async.bulk.tensor.3d.shared::cta.global.tile.mbarrier::complete_tx::bytes " \
        "[%0], [%1, {%2, %3, %4}], [%5];" \
        :: "r"((uint32_t)(smem_addr)), "l"(tmap), "r"((int32_t)(cx)), "r"((int32_t)(cy)), \
           "r"((int32_t)(cz)), "r"((uint32_t)(mbar)) : "memory")

// ---------------- grid barrier (proven R5 version) ----------------
__device__ __forceinline__ void gridbar(unsigned s) {
    __syncthreads();
    if (threadIdx.x == 0) {
        __threadfence();
        unsigned prev = atomicAdd(&g_cnt, 1u);
        if (prev == RNCTA - 1) {
            atomicExch(&g_cnt, 0u);
            __threadfence();
            atomicExch(&g_sense, s);
        } else {
            while (*((volatile unsigned int*)&g_sense) != s) { }
        }
        __threadfence();
    }
    __syncthreads();
}

// ---------------- prep kernels ----------------
__global__ void transpose_x_kernel(const float* __restrict__ x) {
    __shared__ float tile[32][33];
    int b = blockIdx.z, t0 = blockIdx.x * 32, f0 = blockIdx.y * 32;
    const float* xb = x + (size_t)b * Ff * Tt;
    for (int i = threadIdx.y; i < 32; i += 8)
        tile[i][threadIdx.x] = xb[(size_t)(f0 + i) * Tt + t0 + threadIdx.x];
    __syncthreads();
    for (int i = threadIdx.y; i < 32; i += 8)
        g_xT[((size_t)(t0 + i) * Bb + b) * Ff + f0 + threadIdx.x] = tile[threadIdx.x][i];
}

__global__ void whsplit_kernel(const float* __restrict__ Wh) {
    __shared__ float tile[32][33];
    int k0 = blockIdx.x * 32, h0 = blockIdx.y * 32;
    for (int i = threadIdx.y; i < 32; i += 8)
        tile[i][threadIdx.x] = Wh[(size_t)(k0 + i) * Hh + h0 + threadIdx.x];
    __syncthreads();
    for (int i = threadIdx.y; i < 32; i += 8) {
        float w = tile[threadIdx.x][i];
        __nv_bfloat16 hi = __float2bfloat16(w);
        size_t idx = (size_t)(h0 + i) * Hh + k0 + threadIdx.x;
        g_WhiT[idx] = hi;
        g_WloT[idx] = __float2bfloat16(w - __bfloat162float(hi));
    }
}

// U[t][h][b] = bias[h] + sum_f xT[t][b][f] * Wx[f][h]   (f32x2 SIMT GEMM)
__global__ __launch_bounds__(256) void u_gemm_kernel(const float* __restrict__ Wx,
                                                     const float* __restrict__ bias) {
    const int t  = blockIdx.y;
    const int h0 = blockIdx.x * 64;
    __shared__ __align__(16) float As[16][68];
    __shared__ __align__(16) float Bs[16][68];
    const int tid = threadIdx.x;
    const int tx = tid & 15, ty = tid >> 4;
    const int ar = tid >> 4, ac = (tid & 15) * 4;
    const int bbr = tid >> 2, bf = (tid & 3) * 4;
    const float* Xr = g_xT + ((size_t)t * Bb + bbr) * Ff;

    ull acc[4][2];
    #pragma unroll
    for (int i = 0; i < 4; ++i) { acc[i][0] = 0ull; acc[i][1] = 0ull; }
    float4 ra = *(const float4*)(Wx + (size_t)ar * Hh + h0 + ac);
    float4 rb = *(const float4*)(Xr + bf);

    for (int k0 = 0; k0 < Ff; k0 += 16) {
        *(float4*)&As[ar][ac] = ra;
        Bs[bf + 0][bbr] = rb.x; Bs[bf + 1][bbr] = rb.y;
        Bs[bf + 2][bbr] = rb.z; Bs[bf + 3][bbr] = rb.w;
        __syncthreads();
        if (k0 + 16 < Ff) {
            ra = *(const float4*)(Wx + (size_t)(k0 + 16 + ar) * Hh + h0 + ac);
            rb = *(const float4*)(Xr + k0 + 16 + bf);
        }
        #pragma unroll
        for (int kk = 0; kk < 16; ++kk) {
            float4 a = *(const float4*)&As[kk][4 * ty];
            ulonglong2 b2 = *(const ulonglong2*)&Bs[kk][4 * tx];
            float av[4] = {a.x, a.y, a.z, a.w};
            #pragma unroll
            for (int i = 0; i < 4; ++i) {
                ull sp = pk2(av[i], av[i]);
                acc[i][0] = ffma2(sp, b2.x, acc[i][0]);
                acc[i][1] = ffma2(sp, b2.y, acc[i][1]);
            }
        }
        __syncthreads();
    }
    #pragma unroll
    for (int i = 0; i < 4; ++i) {
        float bv = bias[h0 + 4 * ty + i];
        float2 lo = upk2(acc[i][0]), hi = upk2(acc[i][1]);
        float4 v = make_float4(lo.x + bv, lo.y + bv, hi.x + bv, hi.y + bv);
        *(float4*)&g_U[((size_t)t * Hh + h0 + 4 * ty + i) * Bb + 4 * tx] = v;
    }
}

// ---------------- persistent mma.sync recurrence (TMA-fed) ----------------
// tid0: arm mbar[c&1] and issue 8 TMA sub-tile loads (4 hi + 4 lo) for chunk c.
__device__ __forceinline__ void arm_chunk(uint32_t sb, const CUtensorMap* mh,
                                          const CUtensorMap* ml, int c, int z) {
    uint32_t mbar = sb + MB_BASE + (uint32_t)((c & 1) * 8);
    uint32_t dst  = sb + OFF_S + (uint32_t)((c & 1) * BUF_BYTES);
    MBARRIER_EXPECT_TX(mbar, BUF_BYTES);
    #pragma unroll
    for (int s = 0; s < 4; ++s) {
        int k0 = c * KC + s * 64;
        TMA_LOAD_3D(dst + s * 8192,         mh, k0, 0, z, mbar);   // hi sub-tile
        TMA_LOAD_3D(dst + 32768 + s * 8192, ml, k0, 0, z, mbar);   // lo sub-tile
    }
}

__global__ __launch_bounds__(512, 1) void rnn_mma_kernel(
    const __grid_constant__ CUtensorMap map_hi,
    const __grid_constant__ CUtensorMap map_lo)
{
    extern __shared__ __align__(1024) char smem[];
    const uint32_t sb = smem_u32(smem);
    const int tid   = threadIdx.x;
    const int w     = tid >> 5;
    const int lane  = tid & 31;
    const int tile  = w & 7;                  // 8 output tiles
    const int khalf = w >> 3;                 // 0: even 32-k strips, 1: odd
    const int n0    = blockIdx.x * NCOL;
    const int m0    = (tile & 3) * 16;
    const int nw    = (tile >> 2) * 8;

    // mbarrier init (one per buffer)
    if (tid == 0) {
        MBARRIER_INIT(sb + MB_BASE, 1);
        MBARRIER_INIT(sb + MB_BASE + 8, 1);
    }

    // stage Wh^T hi/lo slice (rows n0..n0+15), padded stride (generic path)
    for (int q = tid; q < 16 * 128; q += 512) {
        int r = q >> 7, u = q & 127;
        *(float4*)(smem + OFF_WHI + r * WSTR + u * 16) =
            ((const float4*)g_WhiT)[(size_t)(n0 + r) * 128 + u];
        *(float4*)(smem + OFF_WLO + r * WSTR + u * 16) =
            ((const float4*)g_WloT)[(size_t)(n0 + r) * 128 + u];
    }

    // t = 0: state = tanh(U[0])
    for (int e = tid; e < NCOL * Bb; e += 512) {
        int h = e >> 6, b = e & 63;
        size_t ui = (size_t)(n0 + h) * Bb + b;
        float v = ftanh(g_U[ui]);
        g_U[ui] = v;
        __nv_bfloat16 hi = __float2bfloat16(v);
        g_Sh[0][(size_t)b * Hh + n0 + h] = hi;
        g_Sl[0][(size_t)b * Hh + n0 + h] = __float2bfloat16(v - __bfloat162float(hi));
    }
    asm volatile("fence.proxy.async;" ::: "memory");
    gridbar(1u);

    // per-lane fragment geometry (same mapping as proven R5 kernel)
    const uint32_t rowA  = (uint32_t)(m0 + (lane & 7) + ((lane >> 3) & 1) * 8);
    const uint32_t laneK = (uint32_t)((lane >> 4) * 16);          // bytes (0/16)
    const uint32_t laneX = (rowA & 7u) << 4;                      // SW128 xor term
    const uint32_t rowOff = rowA * 128u;                          // byte row base in tile
    const uint32_t wBhi  = sb + OFF_WHI + (uint32_t)(nw + (lane & 7)) * WSTR
                         + (uint32_t)((lane >> 3) * 16);
    const uint32_t wBlo  = wBhi + (OFF_WLO - OFF_WHI);
    const int r0 = m0 + (lane >> 2);
    const int cA = n0 + nw + 2 * (lane & 3);

    for (int t = 1; t < Tt; ++t) {
        const int zread  = (t - 1) & 1;
        const int zwrite = t & 1;

        // prologue: fill both buffers (chunks 0 and 1)
        if (tid == 0) {
            arm_chunk(sb, &map_hi, &map_lo, 0, zread);
            arm_chunk(sb, &map_hi, &map_lo, 1, zread);
        }

        // prefetch U[t] for epilogue lanes (khalf==0 warps)
        float u00, u01, u10, u11;
        if (khalf == 0) {
            u00 = g_U[((size_t)t * Hh + cA) * Bb + r0];
            u01 = g_U[((size_t)t * Hh + cA + 1) * Bb + r0];
            u10 = g_U[((size_t)t * Hh + cA) * Bb + r0 + 8];
            u11 = g_U[((size_t)t * Hh + cA + 1) * Bb + r0 + 8];
        }

        float ahh[4] = {0.f, 0.f, 0.f, 0.f};
        float ahl[4] = {0.f, 0.f, 0.f, 0.f};
        float alh[4] = {0.f, 0.f, 0.f, 0.f};

        for (int c = 0; c < NCHUNK; ++c) {
            // buffer (c&1), parity: two uses per buffer per step -> (c>>1)
            MBARRIER_WAIT_PARITY(sb + MB_BASE + (uint32_t)((c & 1) * 8),
                                 (unsigned)(c >> 1));
            const uint32_t bufb = sb + OFF_S + (uint32_t)((c & 1) * BUF_BYTES);
            #pragma unroll
            for (int kq = 0; kq < 4; ++kq) {
                int kp = khalf + 2 * kq;
                uint32_t bh[4], bl[4];
                uint32_t wk = (uint32_t)(c * 512 + kp * 64);       // W byte offset
                ldsm4(bh, wBhi + wk);
                ldsm4(bl, wBlo + wk);
                #pragma unroll
                for (int s = 0; s < 2; ++s) {
                    // byte position of this 16B segment within the 512B chunk-row
                    uint32_t kb = (uint32_t)(kp * 64 + s * 32) + laneK;
                    uint32_t aoff = (kb >> 7) * 8192u + rowOff + ((kb & 127u) ^ laneX);
                    uint32_t ahi[4], alo[4];
                    ldsm4(ahi, bufb + aoff);
                    ldsm4(alo, bufb + 32768u + aoff);
                    mma16816(ahh, ahi, bh[2 * s], bh[2 * s + 1]);
                    mma16816(ahl, ahi, bl[2 * s], bl[2 * s + 1]);
                    mma16816(alh, alo, bh[2 * s], bh[2 * s + 1]);
                }
            }
            __syncthreads();          // all warps done with buffer (c&1)
            if (tid == 0 && c + 2 < NCHUNK)
                arm_chunk(sb, &map_hi, &map_lo, c + 2, zread);
        }

        float acc[4];
        #pragma unroll
        for (int i = 0; i < 4; ++i) acc[i] = ahh[i] + ahl[i] + alh[i];

        if (khalf == 1) {
            *(float4*)(smem + OFF_RED + (uint32_t)(tile * 32 + lane) * 16) =
                make_float4(acc[0], acc[1], acc[2], acc[3]);
        }
        __syncthreads();

        if (khalf == 0) {
            float4 p = *(const float4*)(smem + OFF_RED + (uint32_t)(tile * 32 + lane) * 16);
            float s00 = ftanh(u00 + acc[0] + p.x);
            float s01 = ftanh(u01 + acc[1] + p.y);
            float s10 = ftanh(u10 + acc[2] + p.z);
            float s11 = ftanh(u11 + acc[3] + p.w);
            g_U[((size_t)t * Hh + cA) * Bb + r0]         = s00;
            g_U[((size_t)t * Hh + cA + 1) * Bb + r0]     = s01;
            g_U[((size_t)t * Hh + cA) * Bb + r0 + 8]     = s10;
            g_U[((size_t)t * Hh + cA + 1) * Bb + r0 + 8] = s11;
            {
                __nv_bfloat16 h0 = __float2bfloat16(s00), h1 = __float2bfloat16(s01);
                __nv_bfloat162 hp; hp.x = h0; hp.y = h1;
                __nv_bfloat162 lp;
                lp.x = __float2bfloat16(s00 - __bfloat162float(h0));
                lp.y = __float2bfloat16(s01 - __bfloat162float(h1));
                *(__nv_bfloat162*)&g_Sh[zwrite][(size_t)r0 * Hh + cA] = hp;
                *(__nv_bfloat162*)&g_Sl[zwrite][(size_t)r0 * Hh + cA] = lp;
            }
            {
                __nv_bfloat16 h0 = __float2bfloat16(s10), h1 = __float2bfloat16(s11);
                __nv_bfloat162 hp; hp.x = h0; hp.y = h1;
                __nv_bfloat162 lp;
                lp.x = __float2bfloat16(s10 - __bfloat162float(h0));
                lp.y = __float2bfloat16(s11 - __bfloat162float(h1));
                *(__nv_bfloat162*)&g_Sh[zwrite][(size_t)(r0 + 8) * Hh + cA] = hp;
                *(__nv_bfloat162*)&g_Sl[zwrite][(size_t)(r0 + 8) * Hh + cA] = lp;
            }
        }
        asm volatile("fence.proxy.async;" ::: "memory");
        gridbar((unsigned)((t + 1) & 1));
    }
}

// ---------------- output projection (f32x2 SIMT) ----------------
__global__ __launch_bounds__(256) void out_gemm_kernel(const float* __restrict__ Wout,
                                                       const float* __restrict__ bout,
                                                       float* __restrict__ out) {
    const int t  = blockIdx.y;
    const int o0 = blockIdx.x * 64;
    __shared__ __align__(16) float As[16][68];
    __shared__ __align__(16) float Bs[16][68];
    const int tid = threadIdx.x;
    const int tx = tid & 15, ty = tid >> 4;
    const int r = tid >> 4, c = (tid & 15) * 4;

    ull acc[4][2];
    #pragma unroll
    for (int i = 0; i < 4; ++i) { acc[i][0] = 0ull; acc[i][1] = 0ull; }
    float4 ra = *(const float4*)&g_U[((size_t)t * Hh + r) * Bb + c];
    float4 rb = *(const float4*)(Wout + (size_t)r * Oo + o0 + c);

    for (int k0 = 0; k0 < Hh; k0 += 16) {
        *(float4*)&As[r][c] = ra;
        *(float4*)&Bs[r][c] = rb;
        __syncthreads();
        if (k0 + 16 < Hh) {
            ra = *(const float4*)&g_U[((size_t)t * Hh + k0 + 16 + r) * Bb + c];
            rb = *(const float4*)(Wout + (size_t)(k0 + 16 + r) * Oo + o0 + c);
        }
        #pragma unroll
        for (int kk = 0; kk < 16; ++kk) {
            float4 a = *(const float4*)&As[kk][4 * ty];
            ulonglong2 b2 = *(const ulonglong2*)&Bs[kk][4 * tx];
            float av[4] = {a.x, a.y, a.z, a.w};
            #pragma unroll
            for (int i = 0; i < 4; ++i) {
                ull sp = pk2(av[i], av[i]);
                acc[i][0] = ffma2(sp, b2.x, acc[i][0]);
                acc[i][1] = ffma2(sp, b2.y, acc[i][1]);
            }
        }
        __syncthreads();
    }
    float4 bo = *(const float4*)(bout + o0 + 4 * tx);
    #pragma unroll
    for (int i = 0; i < 4; ++i) {
        float2 lo = upk2(acc[i][0]), hi = upk2(acc[i][1]);
        float4 v = make_float4(lo.x + bo.x, lo.y + bo.y, hi.x + bo.z, hi.y + bo.w);
        int b = 4 * ty + i;
        *(float4*)&out[((size_t)b * Tt + t) * Oo + o0 + 4 * tx] = v;
    }
}

// ---------------- host ----------------
typedef CUresult (*EncodeFn)(CUtensorMap*, CUtensorMapDataType, cuuint32_t, void*,
    const cuuint64_t*, const cuuint64_t*, const cuuint32_t*, const cuuint32_t*,
    CUtensorMapInterleave, CUtensorMapSwizzle, CUtensorMapL2promotion, CUtensorMapFloatOOBfill);

extern "C" void kernel_launch(void* const* d_in, const int* in_sizes, int n_in,
                              void* d_out, int out_size) {
    const float* x    = (const float*)d_in[0];
    const float* Wx   = (const float*)d_in[1];
    const float* Wh   = (const float*)d_in[2];
    const float* bias = (const float*)d_in[3];
    const float* Wout = (const float*)d_in[4];
    const float* bout = (const float*)d_in[5];
    float* out = (float*)d_out;

    cudaFuncSetAttribute(rnn_mma_kernel, cudaFuncAttributeMaxDynamicSharedMemorySize, SMEM_TOTAL);

    void *p_shi = nullptr, *p_slo = nullptr;
    cudaGetSymbolAddress(&p_shi, g_Sh);
    cudaGetSymbolAddress(&p_slo, g_Sl);

    EncodeFn enc = nullptr;
    cudaDriverEntryPointQueryResult qr;
    cudaGetDriverEntryPoint("cuTensorMapEncodeTiled", (void**)&enc, cudaEnableDefault, &qr);

    CUtensorMap map_hi, map_lo;
    cuuint64_t dims[3]    = {Hh, Bb, 2};                      // k, b, buffer
    cuuint64_t strides[2] = {Hh * 2, (cuuint64_t)Bb * Hh * 2};
    cuuint32_t box[3]     = {64, Bb, 1};                      // 64 k (128B) x 64 b
    cuuint32_t es[3]      = {1, 1, 1};
    enc(&map_hi, CU_TENSOR_MAP_DATA_TYPE_BFLOAT16, 3, p_shi, dims, strides, box, es,
        CU_TENSOR_MAP_INTERLEAVE_NONE, CU_TENSOR_MAP_SWIZZLE_128B,
        CU_TENSOR_MAP_L2_PROMOTION_L2_128B, CU_TENSOR_MAP_FLOAT_OOB_FILL_NONE);
    enc(&map_lo, CU_TENSOR_MAP_DATA_TYPE_BFLOAT16, 3, p_slo, dims, strides, box, es,
        CU_TENSOR_MAP_INTERLEAVE_NONE, CU_TENSOR_MAP_SWIZZLE_128B,
        CU_TENSOR_MAP_L2_PROMOTION_L2_128B, CU_TENSOR_MAP_FLOAT_OOB_FILL_NONE);

    transpose_x_kernel<<<dim3(Tt / 32, Ff / 32, Bb), dim3(32, 8)>>>(x);
    whsplit_kernel    <<<dim3(Hh / 32, Hh / 32),     dim3(32, 8)>>>(Wh);
    u_gemm_kernel     <<<dim3(Hh / 64, Tt), 256>>>(Wx, bias);
    rnn_mma_kernel    <<<RNCTA, 512, SMEM_TOTAL>>>(map_hi, map_lo);
    out_gemm_kernel   <<<dim3(Oo / 64, Tt), 256>>>(Wout, bout, out);
}

// round 12
// speedup vs baseline: 1.8429x; 1.3739x over previous
#include <cuda_runtime.h>
#include <cuda.h>
#include <cuda_bf16.h>
#include <math.h>
#include <cstdint>

#define Bb 64
#define Ff 256
#define Tt 1024
#define Hh 1024
#define Oo 512
#define RNCTA 128         // 2 b-halves x 64 n-blocks (co-resident single wave)
#define NCOL 16           // hidden columns per recurrence CTA
#define WSTR 2064         // Wh smem row stride bytes (2048 + 16 pad)

// SMEM layout
#define OFF_WHI 0
#define OFF_WLO 33024                     // 16 * WSTR
#define MB_BASE 66048                     // 1 mbarrier
#define OFF_S   66560                     // 1024-aligned; hi 64KB + lo 64KB
#define S_MAT_BYTES 65536                 // 32 b-rows x 1024 k x 2B per matrix
#define OFF_RED (OFF_S + 2 * S_MAT_BYTES) // 197632
#define SMEM_TOTAL (OFF_RED + 12 * 32 * 16)   // +6KB reduction = 203776

typedef unsigned long long ull;

// ---------------- device globals (no allocation allowed) ----------------
__device__ float g_xT[(size_t)Tt * Bb * Ff];          // x as (T,B,F)
__device__ float g_U [(size_t)Tt * Hh * Bb];          // U then fp32 states, [t][h][b]
__device__ __nv_bfloat16 g_WhiT[(size_t)Hh * Hh];     // Wh^T hi  [h][k]
__device__ __nv_bfloat16 g_WloT[(size_t)Hh * Hh];     // Wh^T lo  [h][k]
__device__ __nv_bfloat16 g_Sh[2][(size_t)Bb * Hh];    // state hi, [buf][b][k]
__device__ __nv_bfloat16 g_Sl[2][(size_t)Bb * Hh];    // state lo
__device__ unsigned int g_cnt;                        // legacy grid barrier (end only)
__device__ unsigned int g_sense;
__device__ unsigned int g_flag[RNCTA];                // per-CTA step-completion flags

// ---------------- helpers ----------------
__device__ __forceinline__ uint32_t smem_u32(const void* p) {
    uint32_t a;
    asm("{ .reg .u64 t; cvta.to.shared.u64 t, %1; cvt.u32.u64 %0, t; }" : "=r"(a) : "l"(p));
    return a;
}
__device__ __forceinline__ float ftanh(float x) {
    float xc = fminf(fmaxf(x, -15.0f), 15.0f);
    float e  = __expf(2.0f * xc);
    return __fdividef(e - 1.0f, e + 1.0f);
}
__device__ __forceinline__ ull pk2(float lo, float hi) {
    ull r; asm("mov.b64 %0, {%1, %2};" : "=l"(r) : "f"(lo), "f"(hi)); return r;
}
__device__ __forceinline__ ull ffma2(ull a, ull b, ull c) {
    ull d; asm("fma.rn.f32x2 %0, %1, %2, %3;" : "=l"(d) : "l"(a), "l"(b), "l"(c)); return d;
}
__device__ __forceinline__ float2 upk2(ull v) {
    float2 f; asm("mov.b64 {%0, %1}, %2;" : "=f"(f.x), "=f"(f.y) : "l"(v)); return f;
}

// mma.sync m16n8k16 bf16 -> fp32 (base ISA on compute_103)
__device__ __forceinline__ void mma16816(float* d, const uint32_t* a, uint32_t b0, uint32_t b1) {
    asm volatile("mma.sync.aligned.m16n8k16.row.col.f32.bf16.bf16.f32 "
        "{%0,%1,%2,%3}, {%4,%5,%6,%7}, {%8,%9}, {%0,%1,%2,%3};"
        : "+f"(d[0]), "+f"(d[1]), "+f"(d[2]), "+f"(d[3])
        : "r"(a[0]), "r"(a[1]), "r"(a[2]), "r"(a[3]), "r"(b0), "r"(b1));
}
__device__ __forceinline__ void ldsm4(uint32_t* r, uint32_t addr) {
    asm volatile("ldmatrix.sync.aligned.m8n8.x4.shared.b16 {%0,%1,%2,%3}, [%4];"
        : "=r"(r[0]), "=r"(r[1]), "=r"(r[2]), "=r"(r[3]) : "r"(addr));
}

// ---------------- TMA / mbarrier (base-ISA) ----------------
#define MBARRIER_INIT(mbar, count) \
    asm volatile("mbarrier.init.shared.b64 [%0], %1;" \
        :: "r"((uint32_t)(mbar)), "r"((uint32_t)(count)) : "memory")
#define MBARRIER_EXPECT_TX(mbar, tx) \
    asm volatile("mbarrier.arrive.expect_tx.shared.b64 _, [%0], %1;" \
        :: "r"((uint32_t)(mbar)), "r"((uint32_t)(tx)) : "memory")
#define MBARRIER_WAIT_PARITY(mbar, parity) do {                                    \
    uint32_t _m = (uint32_t)(mbar), _p = (uint32_t)(parity), _done;                \
    asm volatile("{\n\t.reg .pred p;\n\t"                                          \
        "mbarrier.try_wait.parity.acquire.cta.shared::cta.b64 p, [%1], %2;\n\t"    \
        "selp.b32 %0, 1, 0, p;\n\t}"                                               \
        : "=r"(_done) : "r"(_m), "r"(_p) : "memory");                              \
    if (!_done) {                                                                  \
        asm volatile("{\n\t.reg .pred P1;\n\t"                                     \
            "WL_%=:\n\t"                                                           \
            "mbarrier.try_wait.parity.acquire.cta.shared::cta.b64 P1, [%0], %1, 0x989680;\n\t" \
            "@P1 bra.uni WD_%=;\n\t"                                               \
            "bra.uni WL_%=;\n\t"                                                   \
            "WD_%=:\n\t}" :: "r"(_m), "r"(_p) : "memory");                         \
    }                                                                              \
} while (0)
#define TMA_LOAD_3D(smem_addr, tmap, cx, cy, cz, mbar) \
    asm volatile("cp.async.bulk.tensor.3d.shared::cta.global.tile.mbarrier::complete_tx::bytes " \
        "[%0], [%1, {%2, %3, %4}], [%5];" \
        :: "r"((uint32_t)(smem_addr)), "l"(tmap), "r"((int32_t)(cx)), "r"((int32_t)(cy)), \
           "r"((int32_t)(cz)), "r"((uint32_t)(mbar)) : "memory")

// ---------------- legacy grid barrier (end-of-kernel only) ----------------
__device__ __forceinline__ void gridbar(unsigned s) {
    __syncthreads();
    if (threadIdx.x == 0) {
        __threadfence();
        unsigned prev = atomicAdd(&g_cnt, 1u);
        if (prev == RNCTA - 1) {
            atomicExch(&g_cnt, 0u);
            __threadfence();
            atomicExch(&g_sense, s);
        } else {
            while (*((volatile unsigned int*)&g_sense) != s) { }
        }
        __threadfence();
    }
    __syncthreads();
}

// ---------------- prep kernels ----------------
__global__ void transpose_x_kernel(const float* __restrict__ x) {
    __shared__ float tile[32][33];
    int b = blockIdx.z, t0 = blockIdx.x * 32, f0 = blockIdx.y * 32;
    const float* xb = x + (size_t)b * Ff * Tt;
    for (int i = threadIdx.y; i < 32; i += 8)
        tile[i][threadIdx.x] = xb[(size_t)(f0 + i) * Tt + t0 + threadIdx.x];
    __syncthreads();
    for (int i = threadIdx.y; i < 32; i += 8)
        g_xT[((size_t)(t0 + i) * Bb + b) * Ff + f0 + threadIdx.x] = tile[threadIdx.x][i];
}

__global__ void whsplit_kernel(const float* __restrict__ Wh) {
    __shared__ float tile[32][33];
    int k0 = blockIdx.x * 32, h0 = blockIdx.y * 32;
    for (int i = threadIdx.y; i < 32; i += 8)
        tile[i][threadIdx.x] = Wh[(size_t)(k0 + i) * Hh + h0 + threadIdx.x];
    __syncthreads();
    for (int i = threadIdx.y; i < 32; i += 8) {
        float w = tile[threadIdx.x][i];
        __nv_bfloat16 hi = __float2bfloat16(w);
        size_t idx = (size_t)(h0 + i) * Hh + k0 + threadIdx.x;
        g_WhiT[idx] = hi;
        g_WloT[idx] = __float2bfloat16(w - __bfloat162float(hi));
    }
}

// U[t][h][b] = bias[h] + sum_f xT[t][b][f] * Wx[f][h]   (f32x2 SIMT GEMM)
__global__ __launch_bounds__(256) void u_gemm_kernel(const float* __restrict__ Wx,
                                                     const float* __restrict__ bias) {
    const int t  = blockIdx.y;
    const int h0 = blockIdx.x * 64;
    __shared__ __align__(16) float As[16][68];
    __shared__ __align__(16) float Bs[16][68];
    const int tid = threadIdx.x;
    const int tx = tid & 15, ty = tid >> 4;
    const int ar = tid >> 4, ac = (tid & 15) * 4;
    const int bbr = tid >> 2, bf = (tid & 3) * 4;
    const float* Xr = g_xT + ((size_t)t * Bb + bbr) * Ff;

    ull acc[4][2];
    #pragma unroll
    for (int i = 0; i < 4; ++i) { acc[i][0] = 0ull; acc[i][1] = 0ull; }
    float4 ra = *(const float4*)(Wx + (size_t)ar * Hh + h0 + ac);
    float4 rb = *(const float4*)(Xr + bf);

    for (int k0 = 0; k0 < Ff; k0 += 16) {
        *(float4*)&As[ar][ac] = ra;
        Bs[bf + 0][bbr] = rb.x; Bs[bf + 1][bbr] = rb.y;
        Bs[bf + 2][bbr] = rb.z; Bs[bf + 3][bbr] = rb.w;
        __syncthreads();
        if (k0 + 16 < Ff) {
            ra = *(const float4*)(Wx + (size_t)(k0 + 16 + ar) * Hh + h0 + ac);
            rb = *(const float4*)(Xr + k0 + 16 + bf);
        }
        #pragma unroll
        for (int kk = 0; kk < 16; ++kk) {
            float4 a = *(const float4*)&As[kk][4 * ty];
            ulonglong2 b2 = *(const ulonglong2*)&Bs[kk][4 * tx];
            float av[4] = {a.x, a.y, a.z, a.w};
            #pragma unroll
            for (int i = 0; i < 4; ++i) {
                ull sp = pk2(av[i], av[i]);
                acc[i][0] = ffma2(sp, b2.x, acc[i][0]);
                acc[i][1] = ffma2(sp, b2.y, acc[i][1]);
            }
        }
        __syncthreads();
    }
    #pragma unroll
    for (int i = 0; i < 4; ++i) {
        float bv = bias[h0 + 4 * ty + i];
        float2 lo = upk2(acc[i][0]), hi = upk2(acc[i][1]);
        float4 v = make_float4(lo.x + bv, lo.y + bv, hi.x + bv, hi.y + bv);
        *(float4*)&g_U[((size_t)t * Hh + h0 + 4 * ty + i) * Bb + 4 * tx] = v;
    }
}

// ---------------- persistent mma.sync recurrence (b-split, single-shot TMA) ----------------
__global__ __launch_bounds__(512, 1) void rnn_mma_kernel(
    const __grid_constant__ CUtensorMap map_hi,
    const __grid_constant__ CUtensorMap map_lo)
{
    extern __shared__ __align__(1024) char smem[];
    const uint32_t sb = smem_u32(smem);
    const int tid   = threadIdx.x;
    const int w     = tid >> 5;
    const int lane  = tid & 31;
    const int bid   = blockIdx.x;
    const int bhalf = bid >> 6;               // 0 or 1: which 32 batch rows
    const int n0    = (bid & 63) * NCOL;      // hidden-column block
    const int tile  = w & 3;                  // 4 output tiles (2 m x 2 n)
    const int khalf = w >> 2;                 // 0..3: k-quarter of this warp
    const int m0    = (tile & 1) * 16;        // local m base (0..31)
    const int nw    = (tile >> 1) * 8;

    if (tid == 0) MBARRIER_INIT(sb + MB_BASE, 1);

    // stage Wh^T hi/lo slice (rows n0..n0+15)
    for (int q = tid; q < 16 * 128; q += 512) {
        int r = q >> 7, u = q & 127;
        *(float4*)(smem + OFF_WHI + r * WSTR + u * 16) =
            ((const float4*)g_WhiT)[(size_t)(n0 + r) * 128 + u];
        *(float4*)(smem + OFF_WLO + r * WSTR + u * 16) =
            ((const float4*)g_WloT)[(size_t)(n0 + r) * 128 + u];
    }

    // t = 0: state = tanh(U[0]) for this CTA's (b-half, n-block): 16h x 32b
    {
        int h = tid >> 5, bl = tid & 31;              // 512 threads = 16x32
        int bg = bhalf * 32 + bl;
        size_t ui = (size_t)(n0 + h) * Bb + bg;
        float v = ftanh(g_U[ui]);
        g_U[ui] = v;
        __nv_bfloat16 hi = __float2bfloat16(v);
        g_Sh[0][(size_t)bg * Hh + n0 + h] = hi;
        g_Sl[0][(size_t)bg * Hh + n0 + h] = __float2bfloat16(v - __bfloat162float(hi));
    }
    asm volatile("fence.proxy.async;" ::: "memory");
    __threadfence();
    __syncthreads();
    if (tid == 0) atomicExch(&g_flag[bid], 1u);       // release: S_0 slice visible

    // per-lane fragment geometry (local b rows 0..31)
    const uint32_t rowA  = (uint32_t)(m0 + (lane & 7) + ((lane >> 3) & 1) * 8);
    const uint32_t laneK = (uint32_t)((lane >> 4) * 16);          // bytes (0/16)
    const uint32_t laneX = (rowA & 7u) << 4;                      // SW128 xor term
    const uint32_t rowOff = rowA * 128u;                          // row base in 4KB box
    const uint32_t wBhi  = sb + OFF_WHI + (uint32_t)(nw + (lane & 7)) * WSTR
                         + (uint32_t)((lane >> 3) * 16);
    const uint32_t wBlo  = wBhi + (OFF_WLO - OFF_WHI);
    const int r0 = m0 + (lane >> 2);                  // local b row
    const int cA = n0 + nw + 2 * (lane & 3);          // global h col

    for (int t = 1; t < Tt; ++t) {
        const int zread  = (t - 1) & 1;
        const int zwrite = t & 1;

        // flat flag barrier: all CTAs have completed step t-1 (flags >= t)
        if (tid < RNCTA) {
            while (*((volatile unsigned int*)&g_flag[tid]) < (unsigned)t) { }
            __threadfence();
        }
        __syncthreads();

        // single-shot TMA: full 32b x 1024k S slice, hi + lo (32 boxes, 128KB)
        if (tid == 0) {
            MBARRIER_EXPECT_TX(sb + MB_BASE, 2 * S_MAT_BYTES);
            #pragma unroll
            for (int s = 0; s < 16; ++s) {
                TMA_LOAD_3D(sb + OFF_S + s * 4096, &map_hi,
                            s * 64, bhalf * 32, zread, sb + MB_BASE);
                TMA_LOAD_3D(sb + OFF_S + S_MAT_BYTES + s * 4096, &map_lo,
                            s * 64, bhalf * 32, zread, sb + MB_BASE);
            }
        }

        // prefetch U[t] for epilogue lanes (khalf==0 warps) while TMA flies
        float u00, u01, u10, u11;
        if (khalf == 0) {
            int bg = bhalf * 32 + r0;
            u00 = g_U[((size_t)t * Hh + cA) * Bb + bg];
            u01 = g_U[((size_t)t * Hh + cA + 1) * Bb + bg];
            u10 = g_U[((size_t)t * Hh + cA) * Bb + bg + 8];
            u11 = g_U[((size_t)t * Hh + cA + 1) * Bb + bg + 8];
        }

        MBARRIER_WAIT_PARITY(sb + MB_BASE, (unsigned)((t - 1) & 1));

        float ahh[4] = {0.f, 0.f, 0.f, 0.f};
        float ahl[4] = {0.f, 0.f, 0.f, 0.f};
        float alh[4] = {0.f, 0.f, 0.f, 0.f};

        // this warp covers k strips kp = khalf + 4*kq (8 of 32 strips of k32)
        #pragma unroll
        for (int kq = 0; kq < 8; ++kq) {
            int kp = khalf + 4 * kq;
            uint32_t bh[4], bl[4];
            uint32_t wk = (uint32_t)(kp * 64);                 // W byte offset
            ldsm4(bh, wBhi + wk);
            ldsm4(bl, wBlo + wk);
            #pragma unroll
            for (int s = 0; s < 2; ++s) {
                uint32_t kb = (uint32_t)(kp * 64 + s * 32) + laneK;
                uint32_t aoff = (kb >> 7) * 4096u + rowOff + ((kb & 127u) ^ laneX);
                uint32_t ahi[4], alo[4];
                ldsm4(ahi, sb + OFF_S + aoff);
                ldsm4(alo, sb + OFF_S + S_MAT_BYTES + aoff);
                mma16816(ahh, ahi, bh[2 * s], bh[2 * s + 1]);
                mma16816(ahl, ahi, bl[2 * s], bl[2 * s + 1]);
                mma16816(alh, alo, bh[2 * s], bh[2 * s + 1]);
            }
        }

        float acc[4];
        #pragma unroll
        for (int i = 0; i < 4; ++i) acc[i] = ahh[i] + ahl[i] + alh[i];

        // k-reduction: khalf 1..3 publish, khalf 0 combines
        if (khalf != 0) {
            *(float4*)(smem + OFF_RED +
                (uint32_t)(((khalf - 1) * 4 + tile) * 32 + lane) * 16) =
                make_float4(acc[0], acc[1], acc[2], acc[3]);
        }
        __syncthreads();

        if (khalf == 0) {
            #pragma unroll
            for (int kh = 0; kh < 3; ++kh) {
                float4 p = *(const float4*)(smem + OFF_RED +
                    (uint32_t)((kh * 4 + tile) * 32 + lane) * 16);
                acc[0] += p.x; acc[1] += p.y; acc[2] += p.z; acc[3] += p.w;
            }
            int bg = bhalf * 32 + r0;
            float s00 = ftanh(u00 + acc[0]);
            float s01 = ftanh(u01 + acc[1]);
            float s10 = ftanh(u10 + acc[2]);
            float s11 = ftanh(u11 + acc[3]);
            g_U[((size_t)t * Hh + cA) * Bb + bg]         = s00;
            g_U[((size_t)t * Hh + cA + 1) * Bb + bg]     = s01;
            g_U[((size_t)t * Hh + cA) * Bb + bg + 8]     = s10;
            g_U[((size_t)t * Hh + cA + 1) * Bb + bg + 8] = s11;
            {
                __nv_bfloat16 h0 = __float2bfloat16(s00), h1 = __float2bfloat16(s01);
                __nv_bfloat162 hp; hp.x = h0; hp.y = h1;
                __nv_bfloat162 lp;
                lp.x = __float2bfloat16(s00 - __bfloat162float(h0));
                lp.y = __float2bfloat16(s01 - __bfloat162float(h1));
                *(__nv_bfloat162*)&g_Sh[zwrite][(size_t)bg * Hh + cA] = hp;
                *(__nv_bfloat162*)&g_Sl[zwrite][(size_t)bg * Hh + cA] = lp;
            }
            {
                __nv_bfloat16 h0 = __float2bfloat16(s10), h1 = __float2bfloat16(s11);
                __nv_bfloat162 hp; hp.x = h0; hp.y = h1;
                __nv_bfloat162 lp;
                lp.x = __float2bfloat16(s10 - __bfloat162float(h0));
                lp.y = __float2bfloat16(s11 - __bfloat162float(h1));
                *(__nv_bfloat162*)&g_Sh[zwrite][(size_t)(bg + 8) * Hh + cA] = hp;
                *(__nv_bfloat162*)&g_Sl[zwrite][(size_t)(bg + 8) * Hh + cA] = lp;
            }
        }
        // release S_t slice
        asm volatile("fence.proxy.async;" ::: "memory");
        __threadfence();
        __syncthreads();
        if (tid == 0) atomicExch(&g_flag[bid], (unsigned)(t + 1));
    }

    // drain + deterministic flag reset (graph-replay safe)
    gridbar(1u);
    if (bid == 0 && tid < RNCTA) g_flag[tid] = 0u;
    gridbar(0u);
}

// ---------------- output projection (f32x2 SIMT) ----------------
__global__ __launch_bounds__(256) void out_gemm_kernel(const float* __restrict__ Wout,
                                                       const float* __restrict__ bout,
                                                       float* __restrict__ out) {
    const int t  = blockIdx.y;
    const int o0 = blockIdx.x * 64;
    __shared__ __align__(16) float As[16][68];
    __shared__ __align__(16) float Bs[16][68];
    const int tid = threadIdx.x;
    const int tx = tid & 15, ty = tid >> 4;
    const int r = tid >> 4, c = (tid & 15) * 4;

    ull acc[4][2];
    #pragma unroll
    for (int i = 0; i < 4; ++i) { acc[i][0] = 0ull; acc[i][1] = 0ull; }
    float4 ra = *(const float4*)&g_U[((size_t)t * Hh + r) * Bb + c];
    float4 rb = *(const float4*)(Wout + (size_t)r * Oo + o0 + c);

    for (int k0 = 0; k0 < Hh; k0 += 16) {
        *(float4*)&As[r][c] = ra;
        *(float4*)&Bs[r][c] = rb;
        __syncthreads();
        if (k0 + 16 < Hh) {
            ra = *(const float4*)&g_U[((size_t)t * Hh + k0 + 16 + r) * Bb + c];
            rb = *(const float4*)(Wout + (size_t)(k0 + 16 + r) * Oo + o0 + c);
        }
        #pragma unroll
        for (int kk = 0; kk < 16; ++kk) {
            float4 a = *(const float4*)&As[kk][4 * ty];
            ulonglong2 b2 = *(const ulonglong2*)&Bs[kk][4 * tx];
            float av[4] = {a.x, a.y, a.z, a.w};
            #pragma unroll
            for (int i = 0; i < 4; ++i) {
                ull sp = pk2(av[i], av[i]);
                acc[i][0] = ffma2(sp, b2.x, acc[i][0]);
                acc[i][1] = ffma2(sp, b2.y, acc[i][1]);
            }
        }
        __syncthreads();
    }
    float4 bo = *(const float4*)(bout + o0 + 4 * tx);
    #pragma unroll
    for (int i = 0; i < 4; ++i) {
        float2 lo = upk2(acc[i][0]), hi = upk2(acc[i][1]);
        float4 v = make_float4(lo.x + bo.x, lo.y + bo.y, hi.x + bo.z, hi.y + bo.w);
        int b = 4 * ty + i;
        *(float4*)&out[((size_t)b * Tt + t) * Oo + o0 + 4 * tx] = v;
    }
}

// ---------------- host ----------------
typedef CUresult (*EncodeFn)(CUtensorMap*, CUtensorMapDataType, cuuint32_t, void*,
    const cuuint64_t*, const cuuint64_t*, const cuuint32_t*, const cuuint32_t*,
    CUtensorMapInterleave, CUtensorMapSwizzle, CUtensorMapL2promotion, CUtensorMapFloatOOBfill);

extern "C" void kernel_launch(void* const* d_in, const int* in_sizes, int n_in,
                              void* d_out, int out_size) {
    const float* x    = (const float*)d_in[0];
    const float* Wx   = (const float*)d_in[1];
    const float* Wh   = (const float*)d_in[2];
    const float* bias = (const float*)d_in[3];
    const float* Wout = (const float*)d_in[4];
    const float* bout = (const float*)d_in[5];
    float* out = (float*)d_out;

    cudaFuncSetAttribute(rnn_mma_kernel, cudaFuncAttributeMaxDynamicSharedMemorySize, SMEM_TOTAL);

    void *p_shi = nullptr, *p_slo = nullptr;
    cudaGetSymbolAddress(&p_shi, g_Sh);
    cudaGetSymbolAddress(&p_slo, g_Sl);

    EncodeFn enc = nullptr;
    cudaDriverEntryPointQueryResult qr;
    cudaGetDriverEntryPoint("cuTensorMapEncodeTiled", (void**)&enc, cudaEnableDefault, &qr);

    CUtensorMap map_hi, map_lo;
    cuuint64_t dims[3]    = {Hh, Bb, 2};                      // k, b, buffer
    cuuint64_t strides[2] = {Hh * 2, (cuuint64_t)Bb * Hh * 2};
    cuuint32_t box[3]     = {64, 32, 1};                      // 64 k (128B) x 32 b rows
    cuuint32_t es[3]      = {1, 1, 1};
    enc(&map_hi, CU_TENSOR_MAP_DATA_TYPE_BFLOAT16, 3, p_shi, dims, strides, box, es,
        CU_TENSOR_MAP_INTERLEAVE_NONE, CU_TENSOR_MAP_SWIZZLE_128B,
        CU_TENSOR_MAP_L2_PROMOTION_L2_128B, CU_TENSOR_MAP_FLOAT_OOB_FILL_NONE);
    enc(&map_lo, CU_TENSOR_MAP_DATA_TYPE_BFLOAT16, 3, p_slo, dims, strides, box, es,
        CU_TENSOR_MAP_INTERLEAVE_NONE, CU_TENSOR_MAP_SWIZZLE_128B,
        CU_TENSOR_MAP_L2_PROMOTION_L2_128B, CU_TENSOR_MAP_FLOAT_OOB_FILL_NONE);

    transpose_x_kernel<<<dim3(Tt / 32, Ff / 32, Bb), dim3(32, 8)>>>(x);
    whsplit_kernel    <<<dim3(Hh / 32, Hh / 32),     dim3(32, 8)>>>(Wh);
    u_gemm_kernel     <<<dim3(Hh / 64, Tt), 256>>>(Wx, bias);
    rnn_mma_kernel    <<<RNCTA, 512, SMEM_TOTAL>>>(map_hi, map_lo);
    out_gemm_kernel   <<<dim3(Oo / 64, Tt), 256>>>(Wout, bout, out);
}